// round 8
// baseline (speedup 1.0000x reference)
#include <cuda_runtime.h>
#include <cuda_bf16.h>
#include <limits.h>

#define B     8
#define NN    1024
#define EE    1536
#define FIN   64
#define FOUT  64
#define FEDGE 32
#define MAXDEG 24

// ---------------- scratch (static device globals; no allocation) ------------
// Endpoint encoding: g_pmax[e] = max(i)+1, g_pmin[e] = NN - min(i).
// Zero-init means "unset"; atomicMax with identical values every replay is
// idempotent -> no reset needed for these two.
__device__ int   g_pmin[EE];
__device__ int   g_pmax[EE];
__device__ float g_lw[EE];            // lap[src,dst] per edge
__device__ float g_lapii[NN];         // lap diagonal
__device__ float g_ew[B * EE];        // edge scalar weights
__device__ float g_h[B * NN * FOUT];  // nodes @ W
__device__ int   g_cnt[NN];           // adjacency counters (reset in scan blk)
__device__ int   g_adj[NN][MAXDEG];   // packed (e<<10)|j ; row = 96B, 16B aligned

// K1 (fused): blocks [0,256)   = GEMM h = nodes @ W (32 rows x 64 cols each)
//             blocks [256,640) = incidence sweep, 8x LDG.128 batched per thread
#define GEMM_BLOCKS 256
#define SCAN_BLOCKS 384          // 384 * 128 * 8 float4 = NN*EE/4
#define XPAD 68
__global__ void __launch_bounds__(128) k_main(const float* __restrict__ nodes,
                                              const float* __restrict__ W,
                                              const float4* __restrict__ inc4,
                                              const float* __restrict__ lap) {
    __shared__ float4 sW4[FIN][FOUT / 4];   // 16 KB
    __shared__ float  sX[32][XPAD];         // ~8.5 KB
    int tid = threadIdx.x;                  // 128
    int blk = blockIdx.x;

    if (blk >= GEMM_BLOCKS) {
        // ---- scan branch: 8 batched float4 loads (MLP 8), then process ----
        int sb = blk - GEMM_BLOCKS;         // 0..383

        float4 v[8];
        #pragma unroll
        for (int u = 0; u < 8; u++)
            v[u] = inc4[(size_t)(sb * 8 + u) * 128 + tid];

        #pragma unroll
        for (int u = 0; u < 8; u++) {
            int base = ((sb * 8 + u) * 128 + tid) * 4;
            int i = base / EE;
            int e = base - i * EE;
            if (v[u].x != 0.0f) { atomicMax(&g_pmax[e + 0], i + 1); atomicMax(&g_pmin[e + 0], NN - i); }
            if (v[u].y != 0.0f) { atomicMax(&g_pmax[e + 1], i + 1); atomicMax(&g_pmin[e + 1], NN - i); }
            if (v[u].z != 0.0f) { atomicMax(&g_pmax[e + 2], i + 1); atomicMax(&g_pmin[e + 2], NN - i); }
            if (v[u].w != 0.0f) { atomicMax(&g_pmax[e + 3], i + 1); atomicMax(&g_pmin[e + 3], NN - i); }
        }

        if (sb == 0) {
            #pragma unroll
            for (int j = 0; j < NN / 128; j++) {
                int n = tid + j * 128;
                g_cnt[n] = 0;
                g_lapii[n] = lap[n * NN + n];
            }
        }
        return;
    }

    // ---- GEMM branch ----
    int R0 = blk * 32;
    const float4* W4 = (const float4*)W;
    #pragma unroll
    for (int i = 0; i < 8; i++) {
        int idx = tid + i * 128;
        sW4[idx >> 4][idx & 15] = W4[idx];
    }
    const float4* X4 = (const float4*)(nodes + (size_t)R0 * FIN);
    #pragma unroll
    for (int i = 0; i < 4; i++) {
        int idx = tid + i * 128;
        float4 v = X4[idx];
        int row = idx >> 4, c4 = (idx & 15) * 4;
        sX[row][c4 + 0] = v.x; sX[row][c4 + 1] = v.y;
        sX[row][c4 + 2] = v.z; sX[row][c4 + 3] = v.w;
    }
    __syncthreads();

    int tx = tid & 7;
    int ty = tid >> 3;

    float4 a00 = make_float4(0.f,0.f,0.f,0.f), a01 = make_float4(0.f,0.f,0.f,0.f);
    float4 a10 = make_float4(0.f,0.f,0.f,0.f), a11 = make_float4(0.f,0.f,0.f,0.f);

    #pragma unroll
    for (int k = 0; k < FIN; k++) {
        float4 w0 = sW4[k][tx * 2 + 0];
        float4 w1 = sW4[k][tx * 2 + 1];
        float  x0 = sX[ty * 2 + 0][k];
        float  x1 = sX[ty * 2 + 1][k];
        a00.x += x0 * w0.x; a00.y += x0 * w0.y; a00.z += x0 * w0.z; a00.w += x0 * w0.w;
        a01.x += x0 * w1.x; a01.y += x0 * w1.y; a01.z += x0 * w1.z; a01.w += x0 * w1.w;
        a10.x += x1 * w0.x; a10.y += x1 * w0.y; a10.z += x1 * w0.z; a10.w += x1 * w0.w;
        a11.x += x1 * w1.x; a11.y += x1 * w1.y; a11.z += x1 * w1.z; a11.w += x1 * w1.w;
    }

    float4* gh4 = (float4*)g_h;
    int r0 = R0 + ty * 2;
    int o0 = r0 * (FOUT / 4) + tx * 2;
    int o1 = o0 + (FOUT / 4);
    gh4[o0]     = a00;
    gh4[o0 + 1] = a01;
    gh4[o1]     = a10;
    gh4[o1 + 1] = a11;
}

// K2: edge dot products + adjacency build (depends on completed scan).
__global__ void __launch_bounds__(128) k_edge(const float* __restrict__ edges,
                                              const float* __restrict__ evec,
                                              const float* __restrict__ lap) {
    int t = blockIdx.x * 128 + threadIdx.x;          // 0 .. B*EE-1
    int b = t / EE, e = t - b * EE;

    const float4* e4 = (const float4*)(edges + (size_t)t * FEDGE);
    const float4* v4 = (const float4*)evec;
    float s = 0.0f;
    #pragma unroll
    for (int k = 0; k < FEDGE / 4; k++) {
        float4 a = e4[k], v = v4[k];
        s += a.x * v.x + a.y * v.y + a.z * v.z + a.w * v.w;
    }
    g_ew[t] = s;

    if (b == 0) {
        int sn = NN - g_pmin[e];
        int dn = g_pmax[e] - 1;
        g_lw[e] = lap[sn * NN + dn];
        int slot_s = atomicAdd(&g_cnt[sn], 1);
        if (slot_s < MAXDEG) g_adj[sn][slot_s] = (e << 10) | dn;
        int slot_d = atomicAdd(&g_cnt[dn], 1);
        if (slot_d < MAXDEG) g_adj[dn][slot_d] = (e << 10) | sn;
    }
}

// K3: gather assembly of the output, MLP-batched (no atomics).
//     16 threads per (b,i) row, each owns one float4 column group.
__global__ void __launch_bounds__(256) k_gather(float* __restrict__ out) {
    int tid = threadIdx.x;
    int tx  = tid & 15;                       // float4 column group
    int row = (blockIdx.x << 4) + (tid >> 4); // flattened b*NN + i
    int b = row >> 10;
    int i = row & (NN - 1);

    const float4* h4 = (const float4*)g_h;

    int cnt = g_cnt[i];
    if (cnt > MAXDEG) cnt = MAXDEG;

    // Batch-load first 8 adjacency slots (row is 96B, 16B-aligned; slots
    // beyond cnt hold stale-but-in-range packed values or 0 -> predicated off).
    const int4* adj4 = (const int4*)g_adj[i];
    int4 p0 = adj4[0];
    int4 p1 = adj4[1];
    int pk[8] = { p0.x, p0.y, p0.z, p0.w, p1.x, p1.y, p1.z, p1.w };

    // Independent predicated scalar loads: MLP ~16
    float w[8], lw[8];
    #pragma unroll
    for (int k = 0; k < 8; k++) {
        int e = pk[k] >> 10;
        bool ok = k < cnt;
        w[k]  = ok ? __ldg(&g_ew[b * EE + e]) : 0.0f;
        lw[k] = ok ? __ldg(&g_lw[e])          : 0.0f;
    }

    float S = 0.0f;
    #pragma unroll
    for (int k = 0; k < 8; k++) S += w[k];

    // Independent h-row gathers
    float4 acc = make_float4(0.f, 0.f, 0.f, 0.f);
    #pragma unroll
    for (int k = 0; k < 8; k++) {
        if (k < cnt) {
            int j = pk[k] & (NN - 1);
            float c = w[k] * lw[k];
            float4 hv = h4[(size_t)(b * NN + j) * (FOUT / 4) + tx];
            acc.x += c * hv.x; acc.y += c * hv.y; acc.z += c * hv.z; acc.w += c * hv.w;
        }
    }

    // rare tail (deg > 8)
    for (int k = 8; k < cnt; k++) {
        int packed = g_adj[i][k];
        int j = packed & (NN - 1);
        int e = packed >> 10;
        float wv = g_ew[b * EE + e];
        S += wv;
        float c = wv * g_lw[e];
        float4 hv = h4[(size_t)(b * NN + j) * (FOUT / 4) + tx];
        acc.x += c * hv.x; acc.y += c * hv.y; acc.z += c * hv.z; acc.w += c * hv.w;
    }

    float dsc = g_lapii[i] * S;
    float4 hi = h4[(size_t)row * (FOUT / 4) + tx];
    acc.x += dsc * hi.x; acc.y += dsc * hi.y; acc.z += dsc * hi.z; acc.w += dsc * hi.w;

    ((float4*)out)[(size_t)row * (FOUT / 4) + tx] = acc;
}

extern "C" void kernel_launch(void* const* d_in, const int* in_sizes, int n_in,
                              void* d_out, int out_size) {
    const float* nodes = (const float*)d_in[0];   // [B,N,FIN]
    const float* edges = (const float*)d_in[1];   // [B,E,FEDGE]
    const float* W     = (const float*)d_in[2];   // [FIN,FOUT]
    const float* evec  = (const float*)d_in[3];   // [FEDGE]
    const float* inc   = (const float*)d_in[4];   // [N,E]
    const float* lap   = (const float*)d_in[5];   // [N,N]
    float* out = (float*)d_out;                   // [B,N,FOUT]

    k_main<<<GEMM_BLOCKS + SCAN_BLOCKS, 128>>>(nodes, W, (const float4*)inc, lap);
    k_edge<<<(B * EE) / 128, 128>>>(edges, evec, lap);
    k_gather<<<(B * NN) / 16, 256>>>(out);
}

// round 9
// speedup vs baseline: 1.2178x; 1.2178x over previous
#include <cuda_runtime.h>
#include <cuda_bf16.h>
#include <limits.h>

#define B     8
#define NN    1024
#define EE    1536
#define FIN   64
#define FOUT  64
#define FEDGE 32
#define MAXDEG 24

// ---------------- scratch (static device globals; no allocation) ------------
// Endpoint encoding: g_pmax[e] = max(i)+1, g_pmin[e] = NN - min(i).
// Zero-init means "unset"; atomicMax with identical values every replay is
// idempotent -> no reset needed for these two.
__device__ int   g_pmin[EE];
__device__ int   g_pmax[EE];
__device__ float g_lw[EE];            // lap[src,dst] per edge
__device__ float g_lapii[NN];         // lap diagonal
__device__ float g_ew[B * EE];        // edge scalar weights
__device__ float g_h[B * NN * FOUT];  // nodes @ W
__device__ int   g_cnt[NN];           // adjacency counters (reset in scan blk0)
__device__ int   g_adj[NN][MAXDEG];   // packed (e<<10)|j ; row = 96B, 16B aligned

// K1: incidence sweep, 8x LDG.128 batched per thread (MLP 8), no smem,
//     low regs -> high occupancy. 192 blocks x 256 threads x 8 float4 = 6MB.
//     Block 0 also zeroes adjacency counters + gathers lap diagonal.
__global__ void __launch_bounds__(256) k_scan(const float4* __restrict__ inc4,
                                              const float* __restrict__ lap) {
    int tid = threadIdx.x;
    int blk = blockIdx.x;                   // 0..191
    int base4 = blk * 2048;

    float4 v[8];
    #pragma unroll
    for (int u = 0; u < 8; u++)
        v[u] = inc4[base4 + u * 256 + tid];

    #pragma unroll
    for (int u = 0; u < 8; u++) {
        int idx4 = base4 + u * 256 + tid;
        int base = idx4 * 4;
        int i = base / EE;
        int e = base - i * EE;
        if (v[u].x != 0.0f) { atomicMax(&g_pmax[e + 0], i + 1); atomicMax(&g_pmin[e + 0], NN - i); }
        if (v[u].y != 0.0f) { atomicMax(&g_pmax[e + 1], i + 1); atomicMax(&g_pmin[e + 1], NN - i); }
        if (v[u].z != 0.0f) { atomicMax(&g_pmax[e + 2], i + 1); atomicMax(&g_pmin[e + 2], NN - i); }
        if (v[u].w != 0.0f) { atomicMax(&g_pmax[e + 3], i + 1); atomicMax(&g_pmin[e + 3], NN - i); }
    }

    if (blk == 0) {
        #pragma unroll
        for (int j = 0; j < NN / 256; j++) {
            int n = tid + j * 256;
            g_cnt[n] = 0;
            g_lapii[n] = lap[n * NN + n];
        }
    }
}

// K2 (fused): blocks [0,256) = GEMM h = nodes @ W (32 rows x 64 cols per block);
//             blocks [256,352) = edge dot products + adjacency build.
#define GEMM_BLOCKS 256
#define EDGE_BLOCKS ((B * EE) / 128)    // 96
#define XPAD 68
__global__ void __launch_bounds__(128) k_mid(const float* __restrict__ nodes,
                                             const float* __restrict__ W,
                                             const float* __restrict__ edges,
                                             const float* __restrict__ evec,
                                             const float* __restrict__ lap) {
    __shared__ float4 sW4[FIN][FOUT / 4];   // 16 KB
    __shared__ float  sX[32][XPAD];         // ~8.5 KB
    int tid = threadIdx.x;                  // 128
    int blk = blockIdx.x;

    if (blk >= GEMM_BLOCKS) {
        // ---- edge branch: thread per (b,e), 8x float4 dot (MLP 8) ----
        int t = (blk - GEMM_BLOCKS) * 128 + tid;        // 0 .. B*EE-1
        int b = t / EE, e = t - b * EE;

        const float4* e4 = (const float4*)(edges + (size_t)t * FEDGE);
        const float4* v4 = (const float4*)evec;
        float s = 0.0f;
        #pragma unroll
        for (int k = 0; k < FEDGE / 4; k++) {
            float4 a = e4[k], v = v4[k];
            s += a.x * v.x + a.y * v.y + a.z * v.z + a.w * v.w;
        }
        g_ew[t] = s;

        if (b == 0) {
            int sn = NN - g_pmin[e];
            int dn = g_pmax[e] - 1;
            g_lw[e] = lap[sn * NN + dn];
            int slot_s = atomicAdd(&g_cnt[sn], 1);
            if (slot_s < MAXDEG) g_adj[sn][slot_s] = (e << 10) | dn;
            int slot_d = atomicAdd(&g_cnt[dn], 1);
            if (slot_d < MAXDEG) g_adj[dn][slot_d] = (e << 10) | sn;
        }
        return;
    }

    // ---- GEMM branch ----
    int R0 = blk * 32;
    const float4* W4 = (const float4*)W;
    #pragma unroll
    for (int i = 0; i < 8; i++) {
        int idx = tid + i * 128;
        sW4[idx >> 4][idx & 15] = W4[idx];
    }
    const float4* X4 = (const float4*)(nodes + (size_t)R0 * FIN);
    #pragma unroll
    for (int i = 0; i < 4; i++) {
        int idx = tid + i * 128;
        float4 v = X4[idx];
        int row = idx >> 4, c4 = (idx & 15) * 4;
        sX[row][c4 + 0] = v.x; sX[row][c4 + 1] = v.y;
        sX[row][c4 + 2] = v.z; sX[row][c4 + 3] = v.w;
    }
    __syncthreads();

    int tx = tid & 7;
    int ty = tid >> 3;

    float4 a00 = make_float4(0.f,0.f,0.f,0.f), a01 = make_float4(0.f,0.f,0.f,0.f);
    float4 a10 = make_float4(0.f,0.f,0.f,0.f), a11 = make_float4(0.f,0.f,0.f,0.f);

    #pragma unroll
    for (int k = 0; k < FIN; k++) {
        float4 w0 = sW4[k][tx * 2 + 0];
        float4 w1 = sW4[k][tx * 2 + 1];
        float  x0 = sX[ty * 2 + 0][k];
        float  x1 = sX[ty * 2 + 1][k];
        a00.x += x0 * w0.x; a00.y += x0 * w0.y; a00.z += x0 * w0.z; a00.w += x0 * w0.w;
        a01.x += x0 * w1.x; a01.y += x0 * w1.y; a01.z += x0 * w1.z; a01.w += x0 * w1.w;
        a10.x += x1 * w0.x; a10.y += x1 * w0.y; a10.z += x1 * w0.z; a10.w += x1 * w0.w;
        a11.x += x1 * w1.x; a11.y += x1 * w1.y; a11.z += x1 * w1.z; a11.w += x1 * w1.w;
    }

    float4* gh4 = (float4*)g_h;
    int r0 = R0 + ty * 2;
    int o0 = r0 * (FOUT / 4) + tx * 2;
    int o1 = o0 + (FOUT / 4);
    gh4[o0]     = a00;
    gh4[o0 + 1] = a01;
    gh4[o1]     = a10;
    gh4[o1 + 1] = a11;
}

// K3: gather assembly of the output, MLP-batched (no atomics).
//     16 threads per (b,i) row, each owns one float4 column group.
__global__ void __launch_bounds__(256) k_gather(float* __restrict__ out) {
    int tid = threadIdx.x;
    int tx  = tid & 15;                       // float4 column group
    int row = (blockIdx.x << 4) + (tid >> 4); // flattened b*NN + i
    int b = row >> 10;
    int i = row & (NN - 1);

    const float4* h4 = (const float4*)g_h;

    int cnt = g_cnt[i];
    if (cnt > MAXDEG) cnt = MAXDEG;

    // Batch-load first 8 adjacency slots (row is 96B, 16B-aligned; slots
    // beyond cnt hold stale-but-in-range packed values or 0 -> predicated off).
    const int4* adj4 = (const int4*)g_adj[i];
    int4 p0 = adj4[0];
    int4 p1 = adj4[1];
    int pk[8] = { p0.x, p0.y, p0.z, p0.w, p1.x, p1.y, p1.z, p1.w };

    // Independent predicated scalar loads: MLP ~16
    float w[8], lw[8];
    #pragma unroll
    for (int k = 0; k < 8; k++) {
        int e = pk[k] >> 10;
        bool ok = k < cnt;
        w[k]  = ok ? __ldg(&g_ew[b * EE + e]) : 0.0f;
        lw[k] = ok ? __ldg(&g_lw[e])          : 0.0f;
    }

    float S = 0.0f;
    #pragma unroll
    for (int k = 0; k < 8; k++) S += w[k];

    // Independent h-row gathers
    float4 acc = make_float4(0.f, 0.f, 0.f, 0.f);
    #pragma unroll
    for (int k = 0; k < 8; k++) {
        if (k < cnt) {
            int j = pk[k] & (NN - 1);
            float c = w[k] * lw[k];
            float4 hv = h4[(size_t)(b * NN + j) * (FOUT / 4) + tx];
            acc.x += c * hv.x; acc.y += c * hv.y; acc.z += c * hv.z; acc.w += c * hv.w;
        }
    }

    // rare tail (deg > 8)
    for (int k = 8; k < cnt; k++) {
        int packed = g_adj[i][k];
        int j = packed & (NN - 1);
        int e = packed >> 10;
        float wv = g_ew[b * EE + e];
        S += wv;
        float c = wv * g_lw[e];
        float4 hv = h4[(size_t)(b * NN + j) * (FOUT / 4) + tx];
        acc.x += c * hv.x; acc.y += c * hv.y; acc.z += c * hv.z; acc.w += c * hv.w;
    }

    float dsc = g_lapii[i] * S;
    float4 hi = h4[(size_t)row * (FOUT / 4) + tx];
    acc.x += dsc * hi.x; acc.y += dsc * hi.y; acc.z += dsc * hi.z; acc.w += dsc * hi.w;

    ((float4*)out)[(size_t)row * (FOUT / 4) + tx] = acc;
}

extern "C" void kernel_launch(void* const* d_in, const int* in_sizes, int n_in,
                              void* d_out, int out_size) {
    const float* nodes = (const float*)d_in[0];   // [B,N,FIN]
    const float* edges = (const float*)d_in[1];   // [B,E,FEDGE]
    const float* W     = (const float*)d_in[2];   // [FIN,FOUT]
    const float* evec  = (const float*)d_in[3];   // [FEDGE]
    const float* inc   = (const float*)d_in[4];   // [N,E]
    const float* lap   = (const float*)d_in[5];   // [N,N]
    float* out = (float*)d_out;                   // [B,N,FOUT]

    k_scan<<<(NN * EE / 4) / 2048, 256>>>((const float4*)inc, lap);
    k_mid<<<GEMM_BLOCKS + EDGE_BLOCKS, 128>>>(nodes, W, edges, evec, lap);
    k_gather<<<(B * NN) / 16, 256>>>(out);
}